// round 1
// baseline (speedup 1.0000x reference)
#include <cuda_runtime.h>

#define B_   64
#define N_   64
#define C_   8
#define F_   256
#define CF   2048   // C_*F_
#define OCOF 2048   // OC*OF

// ---- scratch (static device arrays; no allocations) ----
__device__ float d_w1sum[F_];
__device__ float d_w2sum[F_];
__device__ float d_s1[B_];
__device__ float d_s2[B_ * N_];
__device__ float d_t[B_ * C_ * F_];          // 0.5 MB
__device__ float d_denom[B_ * F_ * F_];      // 16.8 MB
__device__ float d_zx[B_ * C_ * F_];         // 0.5 MB
__device__ float d_zn[B_ * N_ * C_ * F_];    // 33.5 MB

// K1: column sums of W1/W2 over channels: w1sum[f] = sum_k W1[k,f]
__global__ void k_wsum(const float* __restrict__ W1, const float* __restrict__ W2) {
    int f = threadIdx.x;
    float a = 0.f, b = 0.f;
#pragma unroll
    for (int k = 0; k < C_; k++) { a += W1[k * F_ + f]; b += W2[k * F_ + f]; }
    d_w1sum[f] = a; d_w2sum[f] = b;
}

// K2: s1[b] = sum_{c,f} x[b,c,f]*w1sum[f];  s2[b,n] = sum_{c,f} nb[b,n,c,f]*w2sum[f]
__global__ void k_s12(const float* __restrict__ x, const float* __restrict__ nb) {
    __shared__ float red[256];
    int bid = blockIdx.x;
    int tid = threadIdx.x;
    const float* src;
    const float* wsum;
    if (bid < B_) { src = x + (size_t)bid * CF;          wsum = d_w1sum; }
    else          { src = nb + (size_t)(bid - B_) * CF;  wsum = d_w2sum; }
    float ws = wsum[tid];
    float acc = 0.f;
#pragma unroll
    for (int i = 0; i < C_; i++) acc += src[i * F_ + tid] * ws;  // f == tid
    red[tid] = acc; __syncthreads();
    for (int s = 128; s > 0; s >>= 1) { if (tid < s) red[tid] += red[tid + s]; __syncthreads(); }
    if (tid == 0) { if (bid < B_) d_s1[bid] = red[0]; else d_s2[bid - B_] = red[0]; }
}

// K3: t[b,c,d] = sum_n nb[b,n,c,d] * (s1[b]*s2[b,n])
__global__ void k_t(const float* __restrict__ nb) {
    int b = blockIdx.x >> 3, c = blockIdx.x & 7;
    int d = threadIdx.x;
    __shared__ float ws[N_];
    if (d < N_) ws[d] = d_s1[b] * d_s2[b * N_ + d];
    __syncthreads();
    const float* base = nb + (((size_t)b * N_) * C_ + c) * F_ + d;
    float acc = 0.f;
#pragma unroll 8
    for (int n = 0; n < N_; n++) acc += base[(size_t)n * CF] * ws[n];
    d_t[(b * C_ + c) * F_ + d] = acc;
}

// sgnroot helpers
__device__ __forceinline__ float sgnroot_abs(float v) {
    return (v == 0.f) ? 0.f : sqrtf(fmaxf(fabsf(v), 1e-8f));
}
__device__ __forceinline__ float sgnroot(float v) {
    return (v == 0.f) ? 0.f : copysignf(sqrtf(fmaxf(fabsf(v), 1e-8f)), v);
}

// K4: denom[b,a,d] = 1e-7 + sum_c |sgnroot(x[b,c,a]*t[b,c,d] + x[b,c,d]*t[b,c,a])|
__global__ void k_denom(const float* __restrict__ x) {
    int b = blockIdx.y;
    int slice = blockIdx.x;           // 16 slices of 'a'
    int tid = threadIdx.x;            // = d
    __shared__ float xs[CF], ts[CF];
#pragma unroll
    for (int j = 0; j < 8; j++) {
        xs[tid + j * 256] = x[(size_t)b * CF + tid + j * 256];
        ts[tid + j * 256] = d_t[(size_t)b * CF + tid + j * 256];
    }
    __syncthreads();
    int d = tid;
    for (int ai = 0; ai < 16; ai++) {
        int a = slice * 16 + ai;
        float acc = 0.f;
#pragma unroll
        for (int c = 0; c < C_; c++) {
            float v = xs[c * F_ + a] * ts[c * F_ + d] + xs[c * F_ + d] * ts[c * F_ + a];
            acc += sgnroot_abs(v);
        }
        d_denom[((size_t)b * F_ + a) * F_ + d] = acc + 1e-7f;
    }
}

// K5: per (b,c): recompute adj tiles in smem, produce
//   zn[b,n,c,a] = sum_d adj[a,d]*nb[b,n,c,d]   and   zx[b,c,a] = sum_d adj[a,d]*x[b,c,d]
__global__ void k_zn(const float* __restrict__ x, const float* __restrict__ nb) {
    int b = blockIdx.x >> 3, c = blockIdx.x & 7;
    int tid = threadIdx.x;
    int tx = tid & 15, ty = tid >> 4;
    __shared__ float xS[F_], tS[F_];
    __shared__ float adjS[64][33];
    __shared__ float nbS[64][33];
    xS[tid] = x[(size_t)(b * C_ + c) * F_ + tid];
    tS[tid] = d_t[(size_t)(b * C_ + c) * F_ + tid];
    __syncthreads();

    for (int aT = 0; aT < 4; aT++) {
        float acc[4][4] = {};
        float zxAcc = 0.f;
        for (int dT = 0; dT < 8; dT++) {
            int d0 = dT * 32;
            // build adj tile (64 a x 32 d)
#pragma unroll
            for (int j = 0; j < 8; j++) {
                int i = tid + j * 256;
                int al = i >> 5, dl = i & 31;
                int a = aT * 64 + al, d = d0 + dl;
                float v = xS[a] * tS[d] + xS[d] * tS[a];
                float g = sgnroot(v);
                float den = d_denom[((size_t)b * F_ + a) * F_ + d];
                adjS[al][dl] = __fdividef(g, den);
            }
            // load neighbor tile (64 n x 32 d)
#pragma unroll
            for (int j = 0; j < 8; j++) {
                int i = tid + j * 256;
                int nl = i >> 5, dl = i & 31;
                nbS[nl][dl] = nb[((((size_t)b * N_) + nl) * C_ + c) * F_ + d0 + dl];
            }
            __syncthreads();
#pragma unroll
            for (int kk = 0; kk < 32; kk++) {
                float ar[4], br[4];
#pragma unroll
                for (int u = 0; u < 4; u++) { ar[u] = adjS[tx * 4 + u][kk]; br[u] = nbS[ty * 4 + u][kk]; }
#pragma unroll
                for (int i2 = 0; i2 < 4; i2++)
#pragma unroll
                    for (int j2 = 0; j2 < 4; j2++) acc[i2][j2] += br[i2] * ar[j2];
            }
            if (tid < 64) {
#pragma unroll
                for (int kk = 0; kk < 32; kk++) zxAcc += adjS[tid][kk] * xS[d0 + kk];
            }
            __syncthreads();
        }
#pragma unroll
        for (int i2 = 0; i2 < 4; i2++) {
            int n = ty * 4 + i2;
#pragma unroll
            for (int j2 = 0; j2 < 4; j2++) {
                int a = aT * 64 + tx * 4 + j2;
                d_zn[((((size_t)b * N_) + n) * C_ + c) * F_ + a] = acc[i2][j2];
            }
        }
        if (tid < 64) d_zx[(size_t)(b * C_ + c) * F_ + aT * 64 + tid] = zxAcc;
    }
}

// K6: out[m,o] = sum_k Z[m,k] * Wc[o,k]   (both K-major, K=2048)
// 64x64 tile, BK=16, 256 threads, 4x4 microtile
__global__ void k_gemm(const float* __restrict__ Wc, float* __restrict__ out,
                       int useZx) {
    const float* Z = useZx ? d_zx : d_zn;
    int bo = blockIdx.x * 64;
    int bm = blockIdx.y * 64;
    int tid = threadIdx.x;
    int tx = tid & 15, ty = tid >> 4;
    __shared__ float Zs[16][65];
    __shared__ float Ws[16][65];
    float acc[4][4] = {};
    int r = tid >> 2, c4 = tid & 3;
    const float* zrow = Z + (size_t)(bm + r) * CF + c4 * 4;
    const float* wrow = Wc + (size_t)(bo + r) * CF + c4 * 4;
    for (int k0 = 0; k0 < CF; k0 += 16) {
        float4 vz = *(const float4*)(zrow + k0);
        float4 vw = *(const float4*)(wrow + k0);
        Zs[c4 * 4 + 0][r] = vz.x; Zs[c4 * 4 + 1][r] = vz.y;
        Zs[c4 * 4 + 2][r] = vz.z; Zs[c4 * 4 + 3][r] = vz.w;
        Ws[c4 * 4 + 0][r] = vw.x; Ws[c4 * 4 + 1][r] = vw.y;
        Ws[c4 * 4 + 2][r] = vw.z; Ws[c4 * 4 + 3][r] = vw.w;
        __syncthreads();
#pragma unroll
        for (int kk = 0; kk < 16; kk++) {
            float zr[4], wr[4];
#pragma unroll
            for (int u = 0; u < 4; u++) { zr[u] = Zs[kk][ty * 4 + u]; wr[u] = Ws[kk][tx * 4 + u]; }
#pragma unroll
            for (int i = 0; i < 4; i++)
#pragma unroll
                for (int j = 0; j < 4; j++) acc[i][j] += zr[i] * wr[j];
        }
        __syncthreads();
    }
#pragma unroll
    for (int i = 0; i < 4; i++)
#pragma unroll
        for (int j = 0; j < 4; j++)
            out[(size_t)(bm + ty * 4 + i) * OCOF + bo + tx * 4 + j] = acc[i][j];
}

extern "C" void kernel_launch(void* const* d_in, const int* in_sizes, int n_in,
                              void* d_out, int out_size) {
    (void)in_sizes; (void)n_in; (void)out_size;
    const float* x  = (const float*)d_in[0];  // (B,C,F)
    const float* nb = (const float*)d_in[1];  // (B,N,C,F)
    const float* W1 = (const float*)d_in[2];  // (C,F)
    const float* W2 = (const float*)d_in[3];  // (C,F)
    const float* Wc = (const float*)d_in[4];  // (OC*OF, C, F)
    float* out = (float*)d_out;               // x_out (B,2048) then n_out (B*N,2048)

    k_wsum<<<1, 256>>>(W1, W2);
    k_s12<<<B_ + B_ * N_, 256>>>(x, nb);
    k_t<<<B_ * C_, 256>>>(nb);
    k_denom<<<dim3(16, B_), 256>>>(x);
    k_zn<<<B_ * C_, 256>>>(x, nb);
    // x_out: M=64 rows (zx), out offset 0
    k_gemm<<<dim3(32, 1), 256>>>(Wc, out, 1);
    // n_out: M=4096 rows (zn), out offset B*2048
    k_gemm<<<dim3(32, 64), 256>>>(Wc, out + (size_t)B_ * OCOF, 0);
}

// round 3
// speedup vs baseline: 2.8341x; 2.8341x over previous
#include <cuda_runtime.h>
#include <cstdint>

#define B_   64
#define N_   64
#define C_   8
#define F_   256
#define CF   2048   // C_*F_
#define OCOF 2048   // OC*OF
#define MROWS 4224  // 4096 zn rows + 64 zx rows + 64 zero pad

// ---- scratch (static device arrays; zero-initialized at module load) ----
__device__ float d_w1sum[F_];
__device__ float d_w2sum[F_];
__device__ float d_s1[B_];
__device__ float d_s2[B_ * N_];
__device__ float d_t[B_ * C_ * F_];
__device__ float d_denom[B_ * F_ * F_];
__device__ float d_Z[(size_t)MROWS * CF];     // tf32-rounded; pad rows stay 0
__device__ float d_Wc[(size_t)OCOF * CF];     // tf32-rounded copy of Wc

__device__ __forceinline__ float to_tf32(float v) {
    uint32_t t;
    asm("cvt.rna.tf32.f32 %0, %1;" : "=r"(t) : "f"(v));
    return __uint_as_float(t);
}

// ============================ K1..K5 ============================
__global__ void k_wsum(const float* __restrict__ W1, const float* __restrict__ W2) {
    int f = threadIdx.x;
    float a = 0.f, b = 0.f;
#pragma unroll
    for (int k = 0; k < C_; k++) { a += W1[k * F_ + f]; b += W2[k * F_ + f]; }
    d_w1sum[f] = a; d_w2sum[f] = b;
}

__global__ void k_s12(const float* __restrict__ x, const float* __restrict__ nb) {
    __shared__ float red[256];
    int bid = blockIdx.x;
    int tid = threadIdx.x;
    const float* src;
    const float* wsum;
    if (bid < B_) { src = x + (size_t)bid * CF;          wsum = d_w1sum; }
    else          { src = nb + (size_t)(bid - B_) * CF;  wsum = d_w2sum; }
    float ws = wsum[tid];
    float acc = 0.f;
#pragma unroll
    for (int i = 0; i < C_; i++) acc += src[i * F_ + tid] * ws;
    red[tid] = acc; __syncthreads();
    for (int s = 128; s > 0; s >>= 1) { if (tid < s) red[tid] += red[tid + s]; __syncthreads(); }
    if (tid == 0) { if (bid < B_) d_s1[bid] = red[0]; else d_s2[bid - B_] = red[0]; }
}

__global__ void k_t(const float* __restrict__ nb) {
    int b = blockIdx.x >> 3, c = blockIdx.x & 7;
    int d = threadIdx.x;
    __shared__ float ws[N_];
    if (d < N_) ws[d] = d_s1[b] * d_s2[b * N_ + d];
    __syncthreads();
    const float* base = nb + (((size_t)b * N_) * C_ + c) * F_ + d;
    float acc = 0.f;
#pragma unroll 8
    for (int n = 0; n < N_; n++) acc += base[(size_t)n * CF] * ws[n];
    d_t[(b * C_ + c) * F_ + d] = acc;
}

__device__ __forceinline__ float sgnroot_abs(float v) {
    return (v == 0.f) ? 0.f : sqrtf(fmaxf(fabsf(v), 1e-8f));
}
__device__ __forceinline__ float sgnroot(float v) {
    return (v == 0.f) ? 0.f : copysignf(sqrtf(fmaxf(fabsf(v), 1e-8f)), v);
}

__global__ void k_denom(const float* __restrict__ x) {
    int b = blockIdx.y;
    int slice = blockIdx.x;
    int tid = threadIdx.x;
    __shared__ float xs[CF], ts[CF];
#pragma unroll
    for (int j = 0; j < 8; j++) {
        xs[tid + j * 256] = x[(size_t)b * CF + tid + j * 256];
        ts[tid + j * 256] = d_t[(size_t)b * CF + tid + j * 256];
    }
    __syncthreads();
    int d = tid;
    for (int ai = 0; ai < 16; ai++) {
        int a = slice * 16 + ai;
        float acc = 0.f;
#pragma unroll
        for (int c = 0; c < C_; c++) {
            float v = xs[c * F_ + a] * ts[c * F_ + d] + xs[c * F_ + d] * ts[c * F_ + a];
            acc += sgnroot_abs(v);
        }
        d_denom[((size_t)b * F_ + a) * F_ + d] = acc + 1e-7f;
    }
}

__global__ void k_zn(const float* __restrict__ x, const float* __restrict__ nb) {
    int b = blockIdx.x >> 3, c = blockIdx.x & 7;
    int tid = threadIdx.x;
    int tx = tid & 15, ty = tid >> 4;
    __shared__ float xS[F_], tS[F_];
    __shared__ float adjS[64][33];
    __shared__ float nbS[64][33];
    xS[tid] = x[(size_t)(b * C_ + c) * F_ + tid];
    tS[tid] = d_t[(size_t)(b * C_ + c) * F_ + tid];
    __syncthreads();

    for (int aT = 0; aT < 4; aT++) {
        float acc[4][4] = {};
        float zxAcc = 0.f;
        for (int dT = 0; dT < 8; dT++) {
            int d0 = dT * 32;
#pragma unroll
            for (int j = 0; j < 8; j++) {
                int i = tid + j * 256;
                int al = i >> 5, dl = i & 31;
                int a = aT * 64 + al, d = d0 + dl;
                float v = xS[a] * tS[d] + xS[d] * tS[a];
                float g = sgnroot(v);
                float den = d_denom[((size_t)b * F_ + a) * F_ + d];
                adjS[al][dl] = __fdividef(g, den);
            }
#pragma unroll
            for (int j = 0; j < 8; j++) {
                int i = tid + j * 256;
                int nl = i >> 5, dl = i & 31;
                nbS[nl][dl] = nb[((((size_t)b * N_) + nl) * C_ + c) * F_ + d0 + dl];
            }
            __syncthreads();
#pragma unroll
            for (int kk = 0; kk < 32; kk++) {
                float ar[4], br[4];
#pragma unroll
                for (int u = 0; u < 4; u++) { ar[u] = adjS[tx * 4 + u][kk]; br[u] = nbS[ty * 4 + u][kk]; }
#pragma unroll
                for (int i2 = 0; i2 < 4; i2++)
#pragma unroll
                    for (int j2 = 0; j2 < 4; j2++) acc[i2][j2] += br[i2] * ar[j2];
            }
            if (tid < 64) {
#pragma unroll
                for (int kk = 0; kk < 32; kk++) zxAcc += adjS[tid][kk] * xS[d0 + kk];
            }
            __syncthreads();
        }
#pragma unroll
        for (int i2 = 0; i2 < 4; i2++) {
            int n = ty * 4 + i2;
#pragma unroll
            for (int j2 = 0; j2 < 4; j2++) {
                int a = aT * 64 + tx * 4 + j2;
                d_Z[((((size_t)b * N_) + n) * C_ + c) * F_ + a] = to_tf32(acc[i2][j2]);
            }
        }
        if (tid < 64) d_Z[(size_t)(4096 + b) * CF + c * F_ + aT * 64 + tid] = to_tf32(zxAcc);
    }
}

// Pre-round Wc to tf32 (4 floats / thread)
__global__ void k_wc(const float* __restrict__ Wc) {
    size_t i = ((size_t)blockIdx.x * 256 + threadIdx.x) * 4;
    float4 v = *(const float4*)(Wc + i);
    v.x = to_tf32(v.x); v.y = to_tf32(v.y); v.z = to_tf32(v.z); v.w = to_tf32(v.w);
    *(float4*)(d_Wc + i) = v;
}

// ============================ K6: mma.sync tf32 GEMM ============================
// out[m,o] = sum_k Z[m,k] * Wc[o,k]; M=4224, N=2048, K=2048.
// CTA: 128x128 tile, 256 threads (8 warps, 2x4), warp tile 64x32, BK=32.
#define PITCH 36
#define BUF_F (128 * PITCH)            // floats per buffer per operand
#define GEMM_SMEM (4 * BUF_F * 4)      // bytes: 2 bufs x (A,B)

__device__ __forceinline__ void cp16(uint32_t dst, const float* src) {
    asm volatile("cp.async.cg.shared.global [%0], [%1], 16;" :: "r"(dst), "l"(src));
}
__device__ __forceinline__ uint32_t smem_u32(const void* p) {
    uint32_t a;
    asm("{ .reg .u64 t; cvta.to.shared.u64 t, %1; cvt.u32.u64 %0, t; }" : "=r"(a) : "l"(p));
    return a;
}

__global__ void __launch_bounds__(256, 2) k_gemm_mma(float* __restrict__ out) {
    extern __shared__ float sm[];
    float* AsBuf = sm;                 // [2][128][PITCH]
    float* BsBuf = sm + 2 * BUF_F;     // [2][128][PITCH]
    const int tid = threadIdx.x;
    const int wid = tid >> 5, lid = tid & 31;
    const int wm = wid >> 2, wn = wid & 3;     // warp tile: rows wm*64, cols wn*32
    const int g = lid >> 2, tig = lid & 3;
    const int bm = blockIdx.y * 128, bo = blockIdx.x * 128;

    const int lrow = tid >> 3;         // 0..31
    const int lc4 = tid & 7;           // float4 column
    const uint32_t sA = smem_u32(AsBuf);
    const uint32_t sB = smem_u32(BsBuf);
    const float* Ag = d_Z + (size_t)(bm + lrow) * CF + lc4 * 4;
    const float* Bg = d_Wc + (size_t)(bo + lrow) * CF + lc4 * 4;
    const uint32_t swOff = (uint32_t)(lrow * PITCH + lc4 * 4) * 4;

    float acc[4][4][4];
#pragma unroll
    for (int i = 0; i < 4; i++)
#pragma unroll
        for (int j = 0; j < 4; j++)
#pragma unroll
            for (int k = 0; k < 4; k++) acc[i][j][k] = 0.f;

    const int NKT = CF / 32;           // 64

    // prefetch chunk 0 into buf 0
#pragma unroll
    for (int p = 0; p < 4; p++) {
        cp16(sA + swOff + p * 32 * PITCH * 4, Ag + (size_t)p * 32 * CF);
        cp16(sB + swOff + p * 32 * PITCH * 4, Bg + (size_t)p * 32 * CF);
    }
    asm volatile("cp.async.commit_group;" ::: "memory");

    for (int kt = 0; kt < NKT; kt++) {
        const int buf = kt & 1;
        asm volatile("cp.async.wait_group 0;" ::: "memory");
        __syncthreads();
        if (kt + 1 < NKT) {
            const int nbuf = buf ^ 1;
            const float* Agn = Ag + (kt + 1) * 32;
            const float* Bgn = Bg + (kt + 1) * 32;
#pragma unroll
            for (int p = 0; p < 4; p++) {
                cp16(sA + nbuf * BUF_F * 4 + swOff + p * 32 * PITCH * 4, Agn + (size_t)p * 32 * CF);
                cp16(sB + nbuf * BUF_F * 4 + swOff + p * 32 * PITCH * 4, Bgn + (size_t)p * 32 * CF);
            }
            asm volatile("cp.async.commit_group;" ::: "memory");
        }
        const float* As = AsBuf + buf * BUF_F;
        const float* Bs = BsBuf + buf * BUF_F;
#pragma unroll
        for (int ks = 0; ks < 4; ks++) {
            const int kb = ks * 8 + tig;
            uint32_t a[4][4], b[4][2];
#pragma unroll
            for (int mt = 0; mt < 4; mt++) {
                int r = wm * 64 + mt * 16 + g;
                a[mt][0] = __float_as_uint(As[r * PITCH + kb]);
                a[mt][1] = __float_as_uint(As[(r + 8) * PITCH + kb]);
                a[mt][2] = __float_as_uint(As[r * PITCH + kb + 4]);
                a[mt][3] = __float_as_uint(As[(r + 8) * PITCH + kb + 4]);
            }
#pragma unroll
            for (int nt = 0; nt < 4; nt++) {
                int r = wn * 32 + nt * 8 + g;
                b[nt][0] = __float_as_uint(Bs[r * PITCH + kb]);
                b[nt][1] = __float_as_uint(Bs[r * PITCH + kb + 4]);
            }
#pragma unroll
            for (int mt = 0; mt < 4; mt++)
#pragma unroll
                for (int nt = 0; nt < 4; nt++) {
                    asm volatile(
                        "mma.sync.aligned.m16n8k8.row.col.f32.tf32.tf32.f32 "
                        "{%0,%1,%2,%3}, {%4,%5,%6,%7}, {%8,%9}, {%0,%1,%2,%3};"
                        : "+f"(acc[mt][nt][0]), "+f"(acc[mt][nt][1]),
                          "+f"(acc[mt][nt][2]), "+f"(acc[mt][nt][3])
                        : "r"(a[mt][0]), "r"(a[mt][1]), "r"(a[mt][2]), "r"(a[mt][3]),
                          "r"(b[nt][0]), "r"(b[nt][1]));
                }
        }
        __syncthreads();
    }

    // epilogue: c0,c1 at (row g, col 2*tig,+1); c2,c3 at row g+8
#pragma unroll
    for (int mt = 0; mt < 4; mt++) {
#pragma unroll
        for (int half = 0; half < 2; half++) {
            int m = bm + wm * 64 + mt * 16 + g + half * 8;
            float* dst;
            if (m < 4096)      dst = out + (size_t)B_ * OCOF + (size_t)m * OCOF;
            else if (m < 4160) dst = out + (size_t)(m - 4096) * OCOF;
            else               continue;
#pragma unroll
            for (int nt = 0; nt < 4; nt++) {
                int col = bo + wn * 32 + nt * 8 + 2 * tig;
                float2 v = make_float2(acc[mt][nt][half * 2], acc[mt][nt][half * 2 + 1]);
                *(float2*)(dst + col) = v;
            }
        }
    }
}

// ============================ launch ============================
extern "C" void kernel_launch(void* const* d_in, const int* in_sizes, int n_in,
                              void* d_out, int out_size) {
    (void)in_sizes; (void)n_in; (void)out_size;
    const float* x  = (const float*)d_in[0];
    const float* nb = (const float*)d_in[1];
    const float* W1 = (const float*)d_in[2];
    const float* W2 = (const float*)d_in[3];
    const float* Wc = (const float*)d_in[4];
    float* out = (float*)d_out;

    cudaFuncSetAttribute(k_gemm_mma, cudaFuncAttributeMaxDynamicSharedMemorySize, GEMM_SMEM);

    k_wsum<<<1, 256>>>(W1, W2);
    k_s12<<<B_ + B_ * N_, 256>>>(x, nb);
    k_t<<<B_ * C_, 256>>>(nb);
    k_denom<<<dim3(16, B_), 256>>>(x);
    k_wc<<<(OCOF * CF) / 1024, 256>>>(Wc);
    k_zn<<<B_ * C_, 256>>>(x, nb);
    k_gemm_mma<<<dim3(OCOF / 128, MROWS / 128), 256, GEMM_SMEM>>>(out);
}

// round 4
// speedup vs baseline: 3.2079x; 1.1319x over previous
#include <cuda_runtime.h>
#include <cstdint>

#define B_   64
#define N_   64
#define C_   8
#define F_   256
#define CF   2048   // C_*F_
#define OCOF 2048   // OC*OF
#define MROWS 4224  // 4096 zn rows + 64 zx rows + 64 zero pad

// ---- scratch (static device arrays; zero-initialized at module load) ----
__device__ float d_w1sum[F_];
__device__ float d_w2sum[F_];
__device__ float d_s1[B_];
__device__ float d_s2[B_ * N_];
__device__ float d_t[B_ * C_ * F_];
__device__ float d_denom[B_ * F_ * F_];       // stores RECIPROCAL of denom
__device__ float d_Z[(size_t)MROWS * CF];     // tf32-rounded; pad rows stay 0
__device__ float d_Wc[(size_t)OCOF * CF];     // tf32-rounded copy of Wc

__device__ __forceinline__ float to_tf32(float v) {
    uint32_t t;
    asm("cvt.rna.tf32.f32 %0, %1;" : "=r"(t) : "f"(v));
    return __uint_as_float(t);
}

// ============================ K1..K4 ============================
__global__ void k_wsum(const float* __restrict__ W1, const float* __restrict__ W2) {
    int f = threadIdx.x;
    float a = 0.f, b = 0.f;
#pragma unroll
    for (int k = 0; k < C_; k++) { a += W1[k * F_ + f]; b += W2[k * F_ + f]; }
    d_w1sum[f] = a; d_w2sum[f] = b;
}

__global__ void k_s12(const float* __restrict__ x, const float* __restrict__ nb) {
    __shared__ float red[256];
    int bid = blockIdx.x;
    int tid = threadIdx.x;
    const float* src;
    const float* wsum;
    if (bid < B_) { src = x + (size_t)bid * CF;          wsum = d_w1sum; }
    else          { src = nb + (size_t)(bid - B_) * CF;  wsum = d_w2sum; }
    float ws = wsum[tid];
    float acc = 0.f;
#pragma unroll
    for (int i = 0; i < C_; i++) acc += src[i * F_ + tid] * ws;
    red[tid] = acc; __syncthreads();
    for (int s = 128; s > 0; s >>= 1) { if (tid < s) red[tid] += red[tid + s]; __syncthreads(); }
    if (tid == 0) { if (bid < B_) d_s1[bid] = red[0]; else d_s2[bid - B_] = red[0]; }
}

__global__ void k_t(const float* __restrict__ nb) {
    int b = blockIdx.x >> 3, c = blockIdx.x & 7;
    int d = threadIdx.x;
    __shared__ float ws[N_];
    if (d < N_) ws[d] = d_s1[b] * d_s2[b * N_ + d];
    __syncthreads();
    const float* base = nb + (((size_t)b * N_) * C_ + c) * F_ + d;
    float acc = 0.f;
#pragma unroll 8
    for (int n = 0; n < N_; n++) acc += base[(size_t)n * CF] * ws[n];
    d_t[(b * C_ + c) * F_ + d] = acc;
}

__device__ __forceinline__ float sgnroot_abs(float v) {
    return (v == 0.f) ? 0.f : sqrtf(fmaxf(fabsf(v), 1e-8f));
}
__device__ __forceinline__ float sgnroot(float v) {
    return (v == 0.f) ? 0.f : copysignf(sqrtf(fmaxf(fabsf(v), 1e-8f)), v);
}

// stores reciprocal: d_denom[b,a,d] = 1 / (1e-7 + sum_c |sgnroot(...)|)
__global__ void k_denom(const float* __restrict__ x) {
    int b = blockIdx.y;
    int slice = blockIdx.x;
    int tid = threadIdx.x;
    __shared__ float xs[CF], ts[CF];
#pragma unroll
    for (int j = 0; j < 8; j++) {
        xs[tid + j * 256] = x[(size_t)b * CF + tid + j * 256];
        ts[tid + j * 256] = d_t[(size_t)b * CF + tid + j * 256];
    }
    __syncthreads();
    int d = tid;
    for (int ai = 0; ai < 16; ai++) {
        int a = slice * 16 + ai;
        float acc = 0.f;
#pragma unroll
        for (int c = 0; c < C_; c++) {
            float v = xs[c * F_ + a] * ts[c * F_ + d] + xs[c * F_ + d] * ts[c * F_ + a];
            acc += sgnroot_abs(v);
        }
        d_denom[((size_t)b * F_ + a) * F_ + d] = __fdividef(1.f, acc + 1e-7f);
    }
}

// ============================ K5: tensor-core zn/zx ============================
// Block = (b,c). Output zn[64n x 256a] via m16n8k8 tf32 MMA; adj tiles rebuilt
// in smem per 32-wide d chunk. zx via FFMA on the same adj tiles.
__global__ void __launch_bounds__(256, 2) k_zn_mma(const float* __restrict__ x,
                                                   const float* __restrict__ nb) {
    int b = blockIdx.x >> 3, c = blockIdx.x & 7;
    int tid = threadIdx.x;
    int wid = tid >> 5, lid = tid & 31;
    int g = lid >> 2, tig = lid & 3;
    int A0 = wid * 32;           // warp's a-column range

    __shared__ float xS[F_], tS[F_];
    __shared__ float adjS[F_][33];   // 256a x 32d (+pad)
    __shared__ float nbS[64][33];    // 64n x 32d (+pad)

    xS[tid] = x[(size_t)(b * C_ + c) * F_ + tid];
    tS[tid] = d_t[(size_t)(b * C_ + c) * F_ + tid];
    __syncthreads();

    float acc[4][4][4];
#pragma unroll
    for (int i = 0; i < 4; i++)
#pragma unroll
        for (int j = 0; j < 4; j++)
#pragma unroll
            for (int k = 0; k < 4; k++) acc[i][j][k] = 0.f;
    float zxAcc = 0.f;

    const int dl = tid & 31;
    const int w8 = tid >> 5;     // 0..7

    for (int dt = 0; dt < 8; dt++) {
        const int d0 = dt * 32;
        const float xd = xS[d0 + dl], td = tS[d0 + dl];
        const float* rden = d_denom + (size_t)b * F_ * F_ + d0 + dl;
        // build adj tile: warp shares 'a', lanes span d -> coalesced rden reads
#pragma unroll
        for (int j = 0; j < 32; j++) {
            int a = w8 + j * 8;
            float v = xS[a] * td + xd * tS[a];
            float gg = sgnroot(v);
            adjS[a][dl] = to_tf32(gg * rden[(size_t)a * F_]);
        }
        // load neighbor tile
#pragma unroll
        for (int j = 0; j < 8; j++) {
            int i = tid + j * 256;
            int n = i >> 5, d2 = i & 31;
            nbS[n][d2] = to_tf32(nb[((((size_t)b * N_) + n) * C_ + c) * F_ + d0 + d2]);
        }
        __syncthreads();

#pragma unroll
        for (int ks = 0; ks < 4; ks++) {
            const int kb = ks * 8;
            uint32_t a4[4][4], b2[4][2];
#pragma unroll
            for (int mt = 0; mt < 4; mt++) {
                int r = mt * 16 + g;
                a4[mt][0] = __float_as_uint(nbS[r][kb + tig]);
                a4[mt][1] = __float_as_uint(nbS[r + 8][kb + tig]);
                a4[mt][2] = __float_as_uint(nbS[r][kb + tig + 4]);
                a4[mt][3] = __float_as_uint(nbS[r + 8][kb + tig + 4]);
            }
#pragma unroll
            for (int nt = 0; nt < 4; nt++) {
                int col = A0 + nt * 8 + g;
                b2[nt][0] = __float_as_uint(adjS[col][kb + tig]);
                b2[nt][1] = __float_as_uint(adjS[col][kb + tig + 4]);
            }
#pragma unroll
            for (int mt = 0; mt < 4; mt++)
#pragma unroll
                for (int nt = 0; nt < 4; nt++) {
                    asm volatile(
                        "mma.sync.aligned.m16n8k8.row.col.f32.tf32.tf32.f32 "
                        "{%0,%1,%2,%3}, {%4,%5,%6,%7}, {%8,%9}, {%0,%1,%2,%3};"
                        : "+f"(acc[mt][nt][0]), "+f"(acc[mt][nt][1]),
                          "+f"(acc[mt][nt][2]), "+f"(acc[mt][nt][3])
                        : "r"(a4[mt][0]), "r"(a4[mt][1]), "r"(a4[mt][2]), "r"(a4[mt][3]),
                          "r"(b2[nt][0]), "r"(b2[nt][1]));
                }
        }
        // zx: lane owns a = A0 + lid
        {
            int a = A0 + lid;
#pragma unroll
            for (int k2 = 0; k2 < 32; k2++) zxAcc += adjS[a][k2] * xS[d0 + k2];
        }
        __syncthreads();
    }

    // epilogue: zn rows -> d_Z[((b*64+n)*8+c)*256 + a]
#pragma unroll
    for (int mt = 0; mt < 4; mt++) {
#pragma unroll
        for (int half = 0; half < 2; half++) {
            int n = mt * 16 + g + half * 8;
            float* dst = d_Z + ((((size_t)b * N_) + n) * C_ + c) * F_;
#pragma unroll
            for (int nt = 0; nt < 4; nt++) {
                int col = A0 + nt * 8 + 2 * tig;
                float2 v = make_float2(to_tf32(acc[mt][nt][half * 2]),
                                       to_tf32(acc[mt][nt][half * 2 + 1]));
                *(float2*)(dst + col) = v;
            }
        }
    }
    d_Z[(size_t)(4096 + b) * CF + c * F_ + A0 + lid] = to_tf32(zxAcc);
}

// Pre-round Wc to tf32 (4 floats / thread)
__global__ void k_wc(const float* __restrict__ Wc) {
    size_t i = ((size_t)blockIdx.x * 256 + threadIdx.x) * 4;
    float4 v = *(const float4*)(Wc + i);
    v.x = to_tf32(v.x); v.y = to_tf32(v.y); v.z = to_tf32(v.z); v.w = to_tf32(v.w);
    *(float4*)(d_Wc + i) = v;
}

// ============================ K6: mma.sync tf32 GEMM ============================
// out[m,o] = sum_k Z[m,k] * Wc[o,k]; M=4224, N=2048, K=2048.
#define PITCH 36
#define BUF_F (128 * PITCH)
#define GEMM_SMEM (4 * BUF_F * 4)

__device__ __forceinline__ void cp16(uint32_t dst, const float* src) {
    asm volatile("cp.async.cg.shared.global [%0], [%1], 16;" :: "r"(dst), "l"(src));
}
__device__ __forceinline__ uint32_t smem_u32(const void* p) {
    uint32_t a;
    asm("{ .reg .u64 t; cvta.to.shared.u64 t, %1; cvt.u32.u64 %0, t; }" : "=r"(a) : "l"(p));
    return a;
}

__global__ void __launch_bounds__(256, 2) k_gemm_mma(float* __restrict__ out) {
    extern __shared__ float sm[];
    float* AsBuf = sm;
    float* BsBuf = sm + 2 * BUF_F;
    const int tid = threadIdx.x;
    const int wid = tid >> 5, lid = tid & 31;
    const int wm = wid >> 2, wn = wid & 3;
    const int g = lid >> 2, tig = lid & 3;
    const int bm = blockIdx.y * 128, bo = blockIdx.x * 128;

    const int lrow = tid >> 3;
    const int lc4 = tid & 7;
    const uint32_t sA = smem_u32(AsBuf);
    const uint32_t sB = smem_u32(BsBuf);
    const float* Ag = d_Z + (size_t)(bm + lrow) * CF + lc4 * 4;
    const float* Bg = d_Wc + (size_t)(bo + lrow) * CF + lc4 * 4;
    const uint32_t swOff = (uint32_t)(lrow * PITCH + lc4 * 4) * 4;

    float acc[4][4][4];
#pragma unroll
    for (int i = 0; i < 4; i++)
#pragma unroll
        for (int j = 0; j < 4; j++)
#pragma unroll
            for (int k = 0; k < 4; k++) acc[i][j][k] = 0.f;

    const int NKT = CF / 32;

#pragma unroll
    for (int p = 0; p < 4; p++) {
        cp16(sA + swOff + p * 32 * PITCH * 4, Ag + (size_t)p * 32 * CF);
        cp16(sB + swOff + p * 32 * PITCH * 4, Bg + (size_t)p * 32 * CF);
    }
    asm volatile("cp.async.commit_group;" ::: "memory");

    for (int kt = 0; kt < NKT; kt++) {
        const int buf = kt & 1;
        asm volatile("cp.async.wait_group 0;" ::: "memory");
        __syncthreads();
        if (kt + 1 < NKT) {
            const int nbuf = buf ^ 1;
            const float* Agn = Ag + (kt + 1) * 32;
            const float* Bgn = Bg + (kt + 1) * 32;
#pragma unroll
            for (int p = 0; p < 4; p++) {
                cp16(sA + nbuf * BUF_F * 4 + swOff + p * 32 * PITCH * 4, Agn + (size_t)p * 32 * CF);
                cp16(sB + nbuf * BUF_F * 4 + swOff + p * 32 * PITCH * 4, Bgn + (size_t)p * 32 * CF);
            }
            asm volatile("cp.async.commit_group;" ::: "memory");
        }
        const float* As = AsBuf + buf * BUF_F;
        const float* Bs = BsBuf + buf * BUF_F;
#pragma unroll
        for (int ks = 0; ks < 4; ks++) {
            const int kb = ks * 8 + tig;
            uint32_t a[4][4], b[4][2];
#pragma unroll
            for (int mt = 0; mt < 4; mt++) {
                int r = wm * 64 + mt * 16 + g;
                a[mt][0] = __float_as_uint(As[r * PITCH + kb]);
                a[mt][1] = __float_as_uint(As[(r + 8) * PITCH + kb]);
                a[mt][2] = __float_as_uint(As[r * PITCH + kb + 4]);
                a[mt][3] = __float_as_uint(As[(r + 8) * PITCH + kb + 4]);
            }
#pragma unroll
            for (int nt = 0; nt < 4; nt++) {
                int r = wn * 32 + nt * 8 + g;
                b[nt][0] = __float_as_uint(Bs[r * PITCH + kb]);
                b[nt][1] = __float_as_uint(Bs[r * PITCH + kb + 4]);
            }
#pragma unroll
            for (int mt = 0; mt < 4; mt++)
#pragma unroll
                for (int nt = 0; nt < 4; nt++) {
                    asm volatile(
                        "mma.sync.aligned.m16n8k8.row.col.f32.tf32.tf32.f32 "
                        "{%0,%1,%2,%3}, {%4,%5,%6,%7}, {%8,%9}, {%0,%1,%2,%3};"
                        : "+f"(acc[mt][nt][0]), "+f"(acc[mt][nt][1]),
                          "+f"(acc[mt][nt][2]), "+f"(acc[mt][nt][3])
                        : "r"(a[mt][0]), "r"(a[mt][1]), "r"(a[mt][2]), "r"(a[mt][3]),
                          "r"(b[nt][0]), "r"(b[nt][1]));
                }
        }
        __syncthreads();
    }

#pragma unroll
    for (int mt = 0; mt < 4; mt++) {
#pragma unroll
        for (int half = 0; half < 2; half++) {
            int m = bm + wm * 64 + mt * 16 + g + half * 8;
            float* dst;
            if (m < 4096)      dst = out + (size_t)B_ * OCOF + (size_t)m * OCOF;
            else if (m < 4160) dst = out + (size_t)(m - 4096) * OCOF;
            else               continue;
#pragma unroll
            for (int nt = 0; nt < 4; nt++) {
                int col = bo + wn * 32 + nt * 8 + 2 * tig;
                float2 v = make_float2(acc[mt][nt][half * 2], acc[mt][nt][half * 2 + 1]);
                *(float2*)(dst + col) = v;
            }
        }
    }
}

// ============================ launch ============================
extern "C" void kernel_launch(void* const* d_in, const int* in_sizes, int n_in,
                              void* d_out, int out_size) {
    (void)in_sizes; (void)n_in; (void)out_size;
    const float* x  = (const float*)d_in[0];
    const float* nb = (const float*)d_in[1];
    const float* W1 = (const float*)d_in[2];
    const float* W2 = (const float*)d_in[3];
    const float* Wc = (const float*)d_in[4];
    float* out = (float*)d_out;

    cudaFuncSetAttribute(k_gemm_mma, cudaFuncAttributeMaxDynamicSharedMemorySize, GEMM_SMEM);

    k_wsum<<<1, 256>>>(W1, W2);
    k_s12<<<B_ + B_ * N_, 256>>>(x, nb);
    k_t<<<B_ * C_, 256>>>(nb);
    k_denom<<<dim3(16, B_), 256>>>(x);
    k_wc<<<(OCOF * CF) / 1024, 256>>>(Wc);
    k_zn_mma<<<B_ * C_, 256>>>(x, nb);
    k_gemm_mma<<<dim3(OCOF / 128, MROWS / 128), 256, GEMM_SMEM>>>(out);
}

// round 5
// speedup vs baseline: 4.6789x; 1.4585x over previous
#include <cuda_runtime.h>
#include <cuda_fp16.h>
#include <cstdint>

#define B_   64
#define N_   64
#define C_   8
#define F_   256
#define CF   2048   // C_*F_
#define OCOF 2048   // OC*OF
#define MROWS 4224  // 4096 zn rows + 64 zx rows + 64 zero pad

// ---- scratch (static device arrays; zero-initialized at module load) ----
__device__ float d_w1sum[F_];
__device__ float d_w2sum[F_];
__device__ float d_s1[B_];
__device__ float d_s2[B_ * N_];
__device__ float d_t[B_ * C_ * F_];
__device__ float d_denom[B_ * F_ * F_];        // stores RECIPROCAL of denom
__device__ __half d_Zh[(size_t)MROWS * CF];    // fp16 zn/zx; pad rows stay 0
__device__ __half d_Wch[(size_t)OCOF * CF];    // fp16 copy of Wc

// ============================ K1..K4 ============================
__global__ void k_wsum(const float* __restrict__ W1, const float* __restrict__ W2) {
    int f = threadIdx.x;
    float a = 0.f, b = 0.f;
#pragma unroll
    for (int k = 0; k < C_; k++) { a += W1[k * F_ + f]; b += W2[k * F_ + f]; }
    d_w1sum[f] = a; d_w2sum[f] = b;
}

__global__ void k_s12(const float* __restrict__ x, const float* __restrict__ nb) {
    __shared__ float red[256];
    int bid = blockIdx.x;
    int tid = threadIdx.x;
    const float* src;
    const float* wsum;
    if (bid < B_) { src = x + (size_t)bid * CF;          wsum = d_w1sum; }
    else          { src = nb + (size_t)(bid - B_) * CF;  wsum = d_w2sum; }
    float ws = wsum[tid];
    float acc = 0.f;
#pragma unroll
    for (int i = 0; i < C_; i++) acc += src[i * F_ + tid] * ws;
    red[tid] = acc; __syncthreads();
    for (int s = 128; s > 0; s >>= 1) { if (tid < s) red[tid] += red[tid + s]; __syncthreads(); }
    if (tid == 0) { if (bid < B_) d_s1[bid] = red[0]; else d_s2[bid - B_] = red[0]; }
}

__global__ void k_t(const float* __restrict__ nb) {
    int b = blockIdx.x >> 3, c = blockIdx.x & 7;
    int d = threadIdx.x;
    __shared__ float ws[N_];
    if (d < N_) ws[d] = d_s1[b] * d_s2[b * N_ + d];
    __syncthreads();
    const float* base = nb + (((size_t)b * N_) * C_ + c) * F_ + d;
    float acc = 0.f;
#pragma unroll 8
    for (int n = 0; n < N_; n++) acc += base[(size_t)n * CF] * ws[n];
    d_t[(b * C_ + c) * F_ + d] = acc;
}

__device__ __forceinline__ float sgnroot_abs(float v) {
    return (v == 0.f) ? 0.f : sqrtf(fmaxf(fabsf(v), 1e-8f));
}
__device__ __forceinline__ float sgnroot(float v) {
    return (v == 0.f) ? 0.f : copysignf(sqrtf(fmaxf(fabsf(v), 1e-8f)), v);
}

// stores reciprocal: d_denom[b,a,d] = 1 / (1e-7 + sum_c |sgnroot(...)|)
__global__ void k_denom(const float* __restrict__ x) {
    int b = blockIdx.y;
    int slice = blockIdx.x;
    int tid = threadIdx.x;
    __shared__ float xs[CF], ts[CF];
#pragma unroll
    for (int j = 0; j < 8; j++) {
        xs[tid + j * 256] = x[(size_t)b * CF + tid + j * 256];
        ts[tid + j * 256] = d_t[(size_t)b * CF + tid + j * 256];
    }
    __syncthreads();
    int d = tid;
    for (int ai = 0; ai < 16; ai++) {
        int a = slice * 16 + ai;
        float acc = 0.f;
#pragma unroll
        for (int c = 0; c < C_; c++) {
            float v = xs[c * F_ + a] * ts[c * F_ + d] + xs[c * F_ + d] * ts[c * F_ + a];
            acc += sgnroot_abs(v);
        }
        d_denom[((size_t)b * F_ + a) * F_ + d] = __fdividef(1.f, acc + 1e-7f);
    }
}

// ============================ K5: fp16 tensor-core zn/zx ============================
// Block = (b,c). zn[64n x 256a] via m16n8k16 f16 MMA over d-chunks of 32.
#define APITCH 40   // halves
__global__ void __launch_bounds__(256, 2) k_zn_mma(const float* __restrict__ x,
                                                   const float* __restrict__ nb) {
    int b = blockIdx.x >> 3, c = blockIdx.x & 7;
    int tid = threadIdx.x;
    int wid = tid >> 5, lid = tid & 31;
    int g = lid >> 2, tig = lid & 3;
    int A0 = wid * 32;

    __shared__ float xS[F_], tS[F_];
    __shared__ __half adjS[F_][APITCH];   // 256a x 32d
    __shared__ __half nbS[64][APITCH];    // 64n x 32d

    xS[tid] = x[(size_t)(b * C_ + c) * F_ + tid];
    tS[tid] = d_t[(size_t)(b * C_ + c) * F_ + tid];
    __syncthreads();

    float acc[4][4][4];
#pragma unroll
    for (int i = 0; i < 4; i++)
#pragma unroll
        for (int j = 0; j < 4; j++)
#pragma unroll
            for (int k = 0; k < 4; k++) acc[i][j][k] = 0.f;
    float zxAcc = 0.f;

    const int dl = tid & 31;
    const int w8 = tid >> 5;

    for (int dt = 0; dt < 8; dt++) {
        const int d0 = dt * 32;
        const float xd = xS[d0 + dl], td = tS[d0 + dl];
        const float* rden = d_denom + (size_t)b * F_ * F_ + d0 + dl;
#pragma unroll
        for (int j = 0; j < 32; j++) {
            int a = w8 + j * 8;
            float v = xS[a] * td + xd * tS[a];
            float gg = sgnroot(v);
            adjS[a][dl] = __float2half_rn(gg * rden[(size_t)a * F_]);
        }
#pragma unroll
        for (int j = 0; j < 8; j++) {
            int i = tid + j * 256;
            int n = i >> 5, d2 = i & 31;
            nbS[n][d2] = __float2half_rn(nb[((((size_t)b * N_) + n) * C_ + c) * F_ + d0 + d2]);
        }
        __syncthreads();

#pragma unroll
        for (int ks = 0; ks < 2; ks++) {
            const int kb = ks * 16;
            uint32_t a4[4][4], b2[4][2];
#pragma unroll
            for (int mt = 0; mt < 4; mt++) {
                int r = mt * 16 + g;
                a4[mt][0] = *(const uint32_t*)&nbS[r][kb + 2 * tig];
                a4[mt][1] = *(const uint32_t*)&nbS[r + 8][kb + 2 * tig];
                a4[mt][2] = *(const uint32_t*)&nbS[r][kb + 2 * tig + 8];
                a4[mt][3] = *(const uint32_t*)&nbS[r + 8][kb + 2 * tig + 8];
            }
#pragma unroll
            for (int nt = 0; nt < 4; nt++) {
                int col = A0 + nt * 8 + g;
                b2[nt][0] = *(const uint32_t*)&adjS[col][kb + 2 * tig];
                b2[nt][1] = *(const uint32_t*)&adjS[col][kb + 2 * tig + 8];
            }
#pragma unroll
            for (int mt = 0; mt < 4; mt++)
#pragma unroll
                for (int nt = 0; nt < 4; nt++) {
                    asm volatile(
                        "mma.sync.aligned.m16n8k16.row.col.f32.f16.f16.f32 "
                        "{%0,%1,%2,%3}, {%4,%5,%6,%7}, {%8,%9}, {%0,%1,%2,%3};"
                        : "+f"(acc[mt][nt][0]), "+f"(acc[mt][nt][1]),
                          "+f"(acc[mt][nt][2]), "+f"(acc[mt][nt][3])
                        : "r"(a4[mt][0]), "r"(a4[mt][1]), "r"(a4[mt][2]), "r"(a4[mt][3]),
                          "r"(b2[nt][0]), "r"(b2[nt][1]));
                }
        }
        {
            int a = A0 + lid;
#pragma unroll
            for (int k2 = 0; k2 < 32; k2++) zxAcc += __half2float(adjS[a][k2]) * xS[d0 + k2];
        }
        __syncthreads();
    }

    // epilogue: zn rows -> d_Zh[((b*64+n)*8+c)*256 + a]
#pragma unroll
    for (int mt = 0; mt < 4; mt++) {
#pragma unroll
        for (int half = 0; half < 2; half++) {
            int n = mt * 16 + g + half * 8;
            __half* dst = d_Zh + ((((size_t)b * N_) + n) * C_ + c) * F_;
#pragma unroll
            for (int nt = 0; nt < 4; nt++) {
                int col = A0 + nt * 8 + 2 * tig;
                __half2 v = __floats2half2_rn(acc[mt][nt][half * 2], acc[mt][nt][half * 2 + 1]);
                *(__half2*)(dst + col) = v;
            }
        }
    }
    d_Zh[(size_t)(4096 + b) * CF + c * F_ + A0 + lid] = __float2half_rn(zxAcc);
}

// Convert Wc to fp16 (8 floats / thread)
__global__ void k_wc(const float* __restrict__ Wc) {
    size_t i = ((size_t)blockIdx.x * 256 + threadIdx.x) * 8;
    float4 v0 = *(const float4*)(Wc + i);
    float4 v1 = *(const float4*)(Wc + i + 4);
    __half2 h[4];
    h[0] = __floats2half2_rn(v0.x, v0.y);
    h[1] = __floats2half2_rn(v0.z, v0.w);
    h[2] = __floats2half2_rn(v1.x, v1.y);
    h[3] = __floats2half2_rn(v1.z, v1.w);
    *(uint4*)(d_Wch + i) = *(const uint4*)h;
}

// ============================ K6: fp16 mma GEMM ============================
// out[m,o] = sum_k Z[m,k] * Wc[o,k]; M=4224, N=2048, K=2048.
// CTA 128x128, BK=64 halves (128B/row), 8 warps (2x4), warp tile 64x32.
#define PITCHH 72                       // halves per smem row
#define BUFH (128 * PITCHH)             // halves per buffer per operand
#define GEMM_SMEM (4 * BUFH * 2)        // bytes

__device__ __forceinline__ void cp16(uint32_t dst, const void* src) {
    asm volatile("cp.async.cg.shared.global [%0], [%1], 16;" :: "r"(dst), "l"(src));
}
__device__ __forceinline__ uint32_t smem_u32(const void* p) {
    uint32_t a;
    asm("{ .reg .u64 t; cvta.to.shared.u64 t, %1; cvt.u32.u64 %0, t; }" : "=r"(a) : "l"(p));
    return a;
}

__global__ void __launch_bounds__(256, 2) k_gemm_mma(float* __restrict__ out) {
    extern __shared__ __half smh[];
    __half* AsBuf = smh;                // [2][128][PITCHH]
    __half* BsBuf = smh + 2 * BUFH;
    const int tid = threadIdx.x;
    const int wid = tid >> 5, lid = tid & 31;
    const int wm = wid >> 2, wn = wid & 3;
    const int g = lid >> 2, tig = lid & 3;
    const int bm = blockIdx.y * 128, bo = blockIdx.x * 128;

    const int lrow = tid >> 3;          // 0..31
    const int jc = tid & 7;             // 16B chunk within 128B row
    const uint32_t sA = smem_u32(AsBuf);
    const uint32_t sB = smem_u32(BsBuf);
    const __half* Ag = d_Zh + (size_t)(bm + lrow) * CF + jc * 8;
    const __half* Bg = d_Wch + (size_t)(bo + lrow) * CF + jc * 8;
    const uint32_t swOff = (uint32_t)(lrow * PITCHH + jc * 8) * 2;

    float acc[4][4][4];
#pragma unroll
    for (int i = 0; i < 4; i++)
#pragma unroll
        for (int j = 0; j < 4; j++)
#pragma unroll
            for (int k = 0; k < 4; k++) acc[i][j][k] = 0.f;

    const int NKT = CF / 64;            // 32

#pragma unroll
    for (int p = 0; p < 4; p++) {
        cp16(sA + swOff + p * 32 * PITCHH * 2, Ag + (size_t)p * 32 * CF);
        cp16(sB + swOff + p * 32 * PITCHH * 2, Bg + (size_t)p * 32 * CF);
    }
    asm volatile("cp.async.commit_group;" ::: "memory");

    for (int kt = 0; kt < NKT; kt++) {
        const int buf = kt & 1;
        asm volatile("cp.async.wait_group 0;" ::: "memory");
        __syncthreads();
        if (kt + 1 < NKT) {
            const int nbuf = buf ^ 1;
            const __half* Agn = Ag + (kt + 1) * 64;
            const __half* Bgn = Bg + (kt + 1) * 64;
#pragma unroll
            for (int p = 0; p < 4; p++) {
                cp16(sA + nbuf * BUFH * 2 + swOff + p * 32 * PITCHH * 2, Agn + (size_t)p * 32 * CF);
                cp16(sB + nbuf * BUFH * 2 + swOff + p * 32 * PITCHH * 2, Bgn + (size_t)p * 32 * CF);
            }
            asm volatile("cp.async.commit_group;" ::: "memory");
        }
        const __half* As = AsBuf + buf * BUFH;
        const __half* Bs = BsBuf + buf * BUFH;
#pragma unroll
        for (int ks = 0; ks < 4; ks++) {
            const int kb = ks * 16;
            uint32_t a[4][4], b[4][2];
#pragma unroll
            for (int mt = 0; mt < 4; mt++) {
                int r = wm * 64 + mt * 16 + g;
                a[mt][0] = *(const uint32_t*)&As[r * PITCHH + kb + 2 * tig];
                a[mt][1] = *(const uint32_t*)&As[(r + 8) * PITCHH + kb + 2 * tig];
                a[mt][2] = *(const uint32_t*)&As[r * PITCHH + kb + 2 * tig + 8];
                a[mt][3] = *(const uint32_t*)&As[(r + 8) * PITCHH + kb + 2 * tig + 8];
            }
#pragma unroll
            for (int nt = 0; nt < 4; nt++) {
                int r = wn * 32 + nt * 8 + g;
                b[nt][0] = *(const uint32_t*)&Bs[r * PITCHH + kb + 2 * tig];
                b[nt][1] = *(const uint32_t*)&Bs[r * PITCHH + kb + 2 * tig + 8];
            }
#pragma unroll
            for (int mt = 0; mt < 4; mt++)
#pragma unroll
                for (int nt = 0; nt < 4; nt++) {
                    asm volatile(
                        "mma.sync.aligned.m16n8k16.row.col.f32.f16.f16.f32 "
                        "{%0,%1,%2,%3}, {%4,%5,%6,%7}, {%8,%9}, {%0,%1,%2,%3};"
                        : "+f"(acc[mt][nt][0]), "+f"(acc[mt][nt][1]),
                          "+f"(acc[mt][nt][2]), "+f"(acc[mt][nt][3])
                        : "r"(a[mt][0]), "r"(a[mt][1]), "r"(a[mt][2]), "r"(a[mt][3]),
                          "r"(b[nt][0]), "r"(b[nt][1]));
                }
        }
        __syncthreads();
    }

#pragma unroll
    for (int mt = 0; mt < 4; mt++) {
#pragma unroll
        for (int half = 0; half < 2; half++) {
            int m = bm + wm * 64 + mt * 16 + g + half * 8;
            float* dst;
            if (m < 4096)      dst = out + (size_t)B_ * OCOF + (size_t)m * OCOF;
            else if (m < 4160) dst = out + (size_t)(m - 4096) * OCOF;
            else               continue;
#pragma unroll
            for (int nt = 0; nt < 4; nt++) {
                int col = bo + wn * 32 + nt * 8 + 2 * tig;
                float2 v = make_float2(acc[mt][nt][half * 2], acc[mt][nt][half * 2 + 1]);
                *(float2*)(dst + col) = v;
            }
        }
    }
}

// ============================ launch ============================
extern "C" void kernel_launch(void* const* d_in, const int* in_sizes, int n_in,
                              void* d_out, int out_size) {
    (void)in_sizes; (void)n_in; (void)out_size;
    const float* x  = (const float*)d_in[0];
    const float* nb = (const float*)d_in[1];
    const float* W1 = (const float*)d_in[2];
    const float* W2 = (const float*)d_in[3];
    const float* Wc = (const float*)d_in[4];
    float* out = (float*)d_out;

    cudaFuncSetAttribute(k_gemm_mma, cudaFuncAttributeMaxDynamicSharedMemorySize, GEMM_SMEM);

    k_wsum<<<1, 256>>>(W1, W2);
    k_s12<<<B_ + B_ * N_, 256>>>(x, nb);
    k_t<<<B_ * C_, 256>>>(nb);
    k_denom<<<dim3(16, B_), 256>>>(x);
    k_wc<<<(OCOF * CF) / 2048, 256>>>(Wc);
    k_zn_mma<<<B_ * C_, 256>>>(x, nb);
    k_gemm_mma<<<dim3(OCOF / 128, MROWS / 128), 256, GEMM_SMEM>>>(out);
}

// round 6
// speedup vs baseline: 4.9012x; 1.0475x over previous
#include <cuda_runtime.h>
#include <cuda_fp16.h>
#include <cstdint>

#define B_   64
#define N_   64
#define C_   8
#define F_   256
#define CF   2048   // C_*F_
#define OCOF 2048   // OC*OF
#define MROWS 4224  // 4096 zn rows + 64 zx rows + 64 zero pad

// ---- scratch (static device arrays; zero-initialized at module load) ----
__device__ float d_w1sum[F_];
__device__ float d_w2sum[F_];
__device__ float d_s1[B_];
__device__ float d_s2[B_ * N_];
__device__ float d_t[B_ * C_ * F_];
__device__ float d_denom[B_ * F_ * F_];        // stores RECIPROCAL of denom
__device__ __half d_Zh[(size_t)MROWS * CF];    // fp16 zn/zx; pad rows stay 0
__device__ __half d_Wch[(size_t)OCOF * CF];    // fp16 copy of Wc

__device__ __forceinline__ uint32_t smem_u32(const void* p) {
    uint32_t a;
    asm("{ .reg .u64 t; cvta.to.shared.u64 t, %1; cvt.u32.u64 %0, t; }" : "=r"(a) : "l"(p));
    return a;
}
__device__ __forceinline__ void ldsm4(uint32_t& r0, uint32_t& r1, uint32_t& r2, uint32_t& r3,
                                      uint32_t addr) {
    asm volatile("ldmatrix.sync.aligned.m8n8.x4.shared.b16 {%0,%1,%2,%3}, [%4];"
                 : "=r"(r0), "=r"(r1), "=r"(r2), "=r"(r3) : "r"(addr));
}
__device__ __forceinline__ void cp16(uint32_t dst, const void* src) {
    asm volatile("cp.async.cg.shared.global [%0], [%1], 16;" :: "r"(dst), "l"(src));
}

// ============================ K1..K4 ============================
__global__ void k_wsum(const float* __restrict__ W1, const float* __restrict__ W2) {
    int f = threadIdx.x;
    float a = 0.f, b = 0.f;
#pragma unroll
    for (int k = 0; k < C_; k++) { a += W1[k * F_ + f]; b += W2[k * F_ + f]; }
    d_w1sum[f] = a; d_w2sum[f] = b;
}

__global__ void k_s12(const float* __restrict__ x, const float* __restrict__ nb) {
    __shared__ float red[256];
    int bid = blockIdx.x;
    int tid = threadIdx.x;
    const float* src;
    const float* wsum;
    if (bid < B_) { src = x + (size_t)bid * CF;          wsum = d_w1sum; }
    else          { src = nb + (size_t)(bid - B_) * CF;  wsum = d_w2sum; }
    float ws = wsum[tid];
    float acc = 0.f;
#pragma unroll
    for (int i = 0; i < C_; i++) acc += src[i * F_ + tid] * ws;
    red[tid] = acc; __syncthreads();
    for (int s = 128; s > 0; s >>= 1) { if (tid < s) red[tid] += red[tid + s]; __syncthreads(); }
    if (tid == 0) { if (bid < B_) d_s1[bid] = red[0]; else d_s2[bid - B_] = red[0]; }
}

__global__ void k_t(const float* __restrict__ nb) {
    int b = blockIdx.x >> 3, c = blockIdx.x & 7;
    int d = threadIdx.x;
    __shared__ float ws[N_];
    if (d < N_) ws[d] = d_s1[b] * d_s2[b * N_ + d];
    __syncthreads();
    const float* base = nb + (((size_t)b * N_) * C_ + c) * F_ + d;
    float acc = 0.f;
#pragma unroll 8
    for (int n = 0; n < N_; n++) acc += base[(size_t)n * CF] * ws[n];
    d_t[(b * C_ + c) * F_ + d] = acc;
}

__device__ __forceinline__ float sgnroot_abs(float v) {
    return (v == 0.f) ? 0.f : sqrtf(fmaxf(fabsf(v), 1e-8f));
}
__device__ __forceinline__ float sgnroot(float v) {
    return (v == 0.f) ? 0.f : copysignf(sqrtf(fmaxf(fabsf(v), 1e-8f)), v);
}

__global__ void k_denom(const float* __restrict__ x) {
    int b = blockIdx.y;
    int slice = blockIdx.x;
    int tid = threadIdx.x;
    __shared__ float xs[CF], ts[CF];
#pragma unroll
    for (int j = 0; j < 8; j++) {
        xs[tid + j * 256] = x[(size_t)b * CF + tid + j * 256];
        ts[tid + j * 256] = d_t[(size_t)b * CF + tid + j * 256];
    }
    __syncthreads();
    int d = tid;
    for (int ai = 0; ai < 16; ai++) {
        int a = slice * 16 + ai;
        float acc = 0.f;
#pragma unroll
        for (int c = 0; c < C_; c++) {
            float v = xs[c * F_ + a] * ts[c * F_ + d] + xs[c * F_ + d] * ts[c * F_ + a];
            acc += sgnroot_abs(v);
        }
        d_denom[((size_t)b * F_ + a) * F_ + d] = __fdividef(1.f, acc + 1e-7f);
    }
}

// ============================ K5: fp16 tensor-core zn/zx ============================
#define APITCH 40   // halves
__global__ void __launch_bounds__(256, 2) k_zn_mma(const float* __restrict__ x,
                                                   const float* __restrict__ nb) {
    int b = blockIdx.x >> 3, c = blockIdx.x & 7;
    int tid = threadIdx.x;
    int wid = tid >> 5, lid = tid & 31;
    int g = lid >> 2, tig = lid & 3;
    int A0 = wid * 32;

    __shared__ float xS[F_], tS[F_];
    __shared__ __half adjS[F_][APITCH];
    __shared__ __half nbS[64][APITCH];

    xS[tid] = x[(size_t)(b * C_ + c) * F_ + tid];
    tS[tid] = d_t[(size_t)(b * C_ + c) * F_ + tid];
    __syncthreads();

    float acc[4][4][4];
#pragma unroll
    for (int i = 0; i < 4; i++)
#pragma unroll
        for (int j = 0; j < 4; j++)
#pragma unroll
            for (int k = 0; k < 4; k++) acc[i][j][k] = 0.f;
    float zxAcc = 0.f;

    const int dl = tid & 31;
    const int w8 = tid >> 5;

    // ldmatrix lane addresses (halves offsets -> bytes)
    // A-frag (nbS): row = (lid&15), colSel = (lid>>4)*8
    const uint32_t nbBase = smem_u32(nbS) + ((uint32_t)((lid & 15) * APITCH + (lid >> 4) * 8)) * 2;
    // B-frag (adjS): row = A0 + ((lid>>4)&1)*8 + (lid&7), colSel = ((lid>>3)&1)*8
    const uint32_t adjBase = smem_u32(adjS) +
        ((uint32_t)((A0 + ((lid >> 4) & 1) * 8 + (lid & 7)) * APITCH + ((lid >> 3) & 1) * 8)) * 2;

    for (int dt = 0; dt < 8; dt++) {
        const int d0 = dt * 32;
        const float xd = xS[d0 + dl], td = tS[d0 + dl];
        const float* rden = d_denom + (size_t)b * F_ * F_ + d0 + dl;
#pragma unroll
        for (int j = 0; j < 32; j++) {
            int a = w8 + j * 8;
            float v = xS[a] * td + xd * tS[a];
            float gg = sgnroot(v);
            adjS[a][dl] = __float2half_rn(gg * rden[(size_t)a * F_]);
        }
#pragma unroll
        for (int j = 0; j < 8; j++) {
            int i = tid + j * 256;
            int n = i >> 5, d2 = i & 31;
            nbS[n][d2] = __float2half_rn(nb[((((size_t)b * N_) + n) * C_ + c) * F_ + d0 + d2]);
        }
        __syncthreads();

#pragma unroll
        for (int ks = 0; ks < 2; ks++) {
            const int kb = ks * 16;
            uint32_t a4[4][4], b2[4][2];
#pragma unroll
            for (int mt = 0; mt < 4; mt++)
                ldsm4(a4[mt][0], a4[mt][1], a4[mt][2], a4[mt][3],
                      nbBase + (uint32_t)(mt * 16 * APITCH + kb) * 2);
#pragma unroll
            for (int p = 0; p < 2; p++)
                ldsm4(b2[2 * p][0], b2[2 * p][1], b2[2 * p + 1][0], b2[2 * p + 1][1],
                      adjBase + (uint32_t)(p * 16 * APITCH + kb) * 2);
#pragma unroll
            for (int mt = 0; mt < 4; mt++)
#pragma unroll
                for (int nt = 0; nt < 4; nt++) {
                    asm volatile(
                        "mma.sync.aligned.m16n8k16.row.col.f32.f16.f16.f32 "
                        "{%0,%1,%2,%3}, {%4,%5,%6,%7}, {%8,%9}, {%0,%1,%2,%3};"
                        : "+f"(acc[mt][nt][0]), "+f"(acc[mt][nt][1]),
                          "+f"(acc[mt][nt][2]), "+f"(acc[mt][nt][3])
                        : "r"(a4[mt][0]), "r"(a4[mt][1]), "r"(a4[mt][2]), "r"(a4[mt][3]),
                          "r"(b2[nt][0]), "r"(b2[nt][1]));
                }
        }
        {
            int a = A0 + lid;
#pragma unroll
            for (int k2 = 0; k2 < 32; k2++) zxAcc += __half2float(adjS[a][k2]) * xS[d0 + k2];
        }
        __syncthreads();
    }

#pragma unroll
    for (int mt = 0; mt < 4; mt++) {
#pragma unroll
        for (int half = 0; half < 2; half++) {
            int n = mt * 16 + g + half * 8;
            __half* dst = d_Zh + ((((size_t)b * N_) + n) * C_ + c) * F_;
#pragma unroll
            for (int nt = 0; nt < 4; nt++) {
                int col = A0 + nt * 8 + 2 * tig;
                __half2 v = __floats2half2_rn(acc[mt][nt][half * 2], acc[mt][nt][half * 2 + 1]);
                *(__half2*)(dst + col) = v;
            }
        }
    }
    d_Zh[(size_t)(4096 + b) * CF + c * F_ + A0 + lid] = __float2half_rn(zxAcc);
}

// Convert Wc to fp16 (8 floats / thread)
__global__ void k_wc(const float* __restrict__ Wc) {
    size_t i = ((size_t)blockIdx.x * 256 + threadIdx.x) * 8;
    float4 v0 = *(const float4*)(Wc + i);
    float4 v1 = *(const float4*)(Wc + i + 4);
    __half2 h[4];
    h[0] = __floats2half2_rn(v0.x, v0.y);
    h[1] = __floats2half2_rn(v0.z, v0.w);
    h[2] = __floats2half2_rn(v1.x, v1.y);
    h[3] = __floats2half2_rn(v1.z, v1.w);
    *(uint4*)(d_Wch + i) = *(const uint4*)h;
}

// ============================ K6: fp16 mma GEMM (ldmatrix) ============================
#define PITCHH 72
#define BUFH (128 * PITCHH)
#define GEMM_SMEM (4 * BUFH * 2)

__global__ void __launch_bounds__(256, 2) k_gemm_mma(float* __restrict__ out) {
    extern __shared__ __half smh[];
    __half* AsBuf = smh;
    __half* BsBuf = smh + 2 * BUFH;
    const int tid = threadIdx.x;
    const int wid = tid >> 5, lid = tid & 31;
    const int wm = wid >> 2, wn = wid & 3;
    const int g = lid >> 2, tig = lid & 3;
    const int bm = blockIdx.y * 128, bo = blockIdx.x * 128;

    const int lrow = tid >> 3;
    const int jc = tid & 7;
    const uint32_t sA = smem_u32(AsBuf);
    const uint32_t sB = smem_u32(BsBuf);
    const __half* Ag = d_Zh + (size_t)(bm + lrow) * CF + jc * 8;
    const __half* Bg = d_Wch + (size_t)(bo + lrow) * CF + jc * 8;
    const uint32_t swOff = (uint32_t)(lrow * PITCHH + jc * 8) * 2;

    // ldmatrix lane bases
    const uint32_t aBase = sA + ((uint32_t)((wm * 64 + (lid & 15)) * PITCHH + (lid >> 4) * 8)) * 2;
    const uint32_t bBase = sB + ((uint32_t)((wn * 32 + ((lid >> 4) & 1) * 8 + (lid & 7)) * PITCHH +
                                            ((lid >> 3) & 1) * 8)) * 2;

    float acc[4][4][4];
#pragma unroll
    for (int i = 0; i < 4; i++)
#pragma unroll
        for (int j = 0; j < 4; j++)
#pragma unroll
            for (int k = 0; k < 4; k++) acc[i][j][k] = 0.f;

    const int NKT = CF / 64;   // 32

#pragma unroll
    for (int p = 0; p < 4; p++) {
        cp16(sA + swOff + p * 32 * PITCHH * 2, Ag + (size_t)p * 32 * CF);
        cp16(sB + swOff + p * 32 * PITCHH * 2, Bg + (size_t)p * 32 * CF);
    }
    asm volatile("cp.async.commit_group;" ::: "memory");

    for (int kt = 0; kt < NKT; kt++) {
        const int buf = kt & 1;
        asm volatile("cp.async.wait_group 0;" ::: "memory");
        __syncthreads();
        if (kt + 1 < NKT) {
            const int nbuf = buf ^ 1;
            const __half* Agn = Ag + (kt + 1) * 64;
            const __half* Bgn = Bg + (kt + 1) * 64;
#pragma unroll
            for (int p = 0; p < 4; p++) {
                cp16(sA + nbuf * BUFH * 2 + swOff + p * 32 * PITCHH * 2, Agn + (size_t)p * 32 * CF);
                cp16(sB + nbuf * BUFH * 2 + swOff + p * 32 * PITCHH * 2, Bgn + (size_t)p * 32 * CF);
            }
            asm volatile("cp.async.commit_group;" ::: "memory");
        }
        const uint32_t aB = aBase + (uint32_t)buf * BUFH * 2;
        const uint32_t bB = bBase + (uint32_t)buf * BUFH * 2;
#pragma unroll
        for (int ks = 0; ks < 4; ks++) {
            const uint32_t kOff = (uint32_t)(ks * 16) * 2;
            uint32_t a[4][4], b[4][2];
#pragma unroll
            for (int mt = 0; mt < 4; mt++)
                ldsm4(a[mt][0], a[mt][1], a[mt][2], a[mt][3],
                      aB + (uint32_t)(mt * 16 * PITCHH) * 2 + kOff);
#pragma unroll
            for (int p = 0; p < 2; p++)
                ldsm4(b[2 * p][0], b[2 * p][1], b[2 * p + 1][0], b[2 * p + 1][1],
                      bB + (uint32_t)(p * 16 * PITCHH) * 2 + kOff);
#pragma unroll
            for (int mt = 0; mt < 4; mt++)
#pragma unroll
                for (int nt = 0; nt < 4; nt++) {
                    asm volatile(
                        "mma.sync.aligned.m16n8k16.row.col.f32.f16.f16.f32 "
                        "{%0,%1,%2,%3}, {%4,%5,%6,%7}, {%8,%9}, {%0,%1,%2,%3};"
                        : "+f"(acc[mt][nt][0]), "+f"(acc[mt][nt][1]),
                          "+f"(acc[mt][nt][2]), "+f"(acc[mt][nt][3])
                        : "r"(a[mt][0]), "r"(a[mt][1]), "r"(a[mt][2]), "r"(a[mt][3]),
                          "r"(b[nt][0]), "r"(b[nt][1]));
                }
        }
        __syncthreads();
    }

#pragma unroll
    for (int mt = 0; mt < 4; mt++) {
#pragma unroll
        for (int half = 0; half < 2; half++) {
            int m = bm + wm * 64 + mt * 16 + g + half * 8;
            float* dst;
            if (m < 4096)      dst = out + (size_t)B_ * OCOF + (size_t)m * OCOF;
            else if (m < 4160) dst = out + (size_t)(m - 4096) * OCOF;
            else               continue;
#pragma unroll
            for (int nt = 0; nt < 4; nt++) {
                int col = bo + wn * 32 + nt * 8 + 2 * tig;
                float2 v = make_float2(acc[mt][nt][half * 2], acc[mt][nt][half * 2 + 1]);
                *(float2*)(dst + col) = v;
            }
        }
    }
}

// ============================ launch ============================
extern "C" void kernel_launch(void* const* d_in, const int* in_sizes, int n_in,
                              void* d_out, int out_size) {
    (void)in_sizes; (void)n_in; (void)out_size;
    const float* x  = (const float*)d_in[0];
    const float* nb = (const float*)d_in[1];
    const float* W1 = (const float*)d_in[2];
    const float* W2 = (const float*)d_in[3];
    const float* Wc = (const float*)d_in[4];
    float* out = (float*)d_out;

    cudaFuncSetAttribute(k_gemm_mma, cudaFuncAttributeMaxDynamicSharedMemorySize, GEMM_SMEM);

    k_wsum<<<1, 256>>>(W1, W2);
    k_s12<<<B_ + B_ * N_, 256>>>(x, nb);
    k_t<<<B_ * C_, 256>>>(nb);
    k_denom<<<dim3(16, B_), 256>>>(x);
    k_wc<<<(OCOF * CF) / 2048, 256>>>(Wc);
    k_zn_mma<<<B_ * C_, 256>>>(x, nb);
    k_gemm_mma<<<dim3(OCOF / 128, MROWS / 128), 256, GEMM_SMEM>>>(out);
}

// round 7
// speedup vs baseline: 5.2080x; 1.0626x over previous
#include <cuda_runtime.h>
#include <cuda_fp16.h>
#include <cstdint>

#define B_   64
#define N_   64
#define C_   8
#define F_   256
#define CF   2048   // C_*F_
#define OCOF 2048   // OC*OF
#define MROWS 4224  // 4096 zn rows + 64 zx rows + 64 zero pad

// ---- scratch (static device arrays; zero-initialized at module load) ----
__device__ float d_s1[B_];
__device__ float d_s2[B_ * N_];
__device__ float d_t[B_ * C_ * F_];
__device__ __half d_denomh[B_ * F_ * F_];      // RECIPROCAL of denom, fp16
__device__ __half d_Zh[(size_t)MROWS * CF];    // fp16 zn/zx; pad rows stay 0
__device__ __half d_Wch[(size_t)OCOF * CF];    // fp16 copy of Wc

__device__ __forceinline__ uint32_t smem_u32(const void* p) {
    uint32_t a;
    asm("{ .reg .u64 t; cvta.to.shared.u64 t, %1; cvt.u32.u64 %0, t; }" : "=r"(a) : "l"(p));
    return a;
}
__device__ __forceinline__ void ldsm4(uint32_t& r0, uint32_t& r1, uint32_t& r2, uint32_t& r3,
                                      uint32_t addr) {
    asm volatile("ldmatrix.sync.aligned.m8n8.x4.shared.b16 {%0,%1,%2,%3}, [%4];"
                 : "=r"(r0), "=r"(r1), "=r"(r2), "=r"(r3) : "r"(addr));
}
__device__ __forceinline__ void cp16(uint32_t dst, const void* src) {
    asm volatile("cp.async.cg.shared.global [%0], [%1], 16;" :: "r"(dst), "l"(src));
}

// ============================ K1: s1/s2 (wsum fused) ============================
__global__ void k_s12(const float* __restrict__ x, const float* __restrict__ nb,
                      const float* __restrict__ W1, const float* __restrict__ W2) {
    __shared__ float red[256];
    int bid = blockIdx.x;
    int tid = threadIdx.x;
    const float* src;
    const float* W;
    if (bid < B_) { src = x + (size_t)bid * CF;          W = W1; }
    else          { src = nb + (size_t)(bid - B_) * CF;  W = W2; }
    float ws = 0.f;
#pragma unroll
    for (int k = 0; k < C_; k++) ws += W[k * F_ + tid];
    float acc = 0.f;
#pragma unroll
    for (int i = 0; i < C_; i++) acc += src[i * F_ + tid] * ws;
    red[tid] = acc; __syncthreads();
    for (int s = 128; s > 0; s >>= 1) { if (tid < s) red[tid] += red[tid + s]; __syncthreads(); }
    if (tid == 0) { if (bid < B_) d_s1[bid] = red[0]; else d_s2[bid - B_] = red[0]; }
}

__global__ void k_t(const float* __restrict__ nb) {
    int b = blockIdx.x >> 3, c = blockIdx.x & 7;
    int d = threadIdx.x;
    __shared__ float ws[N_];
    if (d < N_) ws[d] = d_s1[b] * d_s2[b * N_ + d];
    __syncthreads();
    const float* base = nb + (((size_t)b * N_) * C_ + c) * F_ + d;
    float acc = 0.f;
#pragma unroll 8
    for (int n = 0; n < N_; n++) acc += base[(size_t)n * CF] * ws[n];
    d_t[(b * C_ + c) * F_ + d] = acc;
}

__device__ __forceinline__ float sgnroot_abs(float v) {
    return (v == 0.f) ? 0.f : sqrtf(fmaxf(fabsf(v), 1e-8f));
}
__device__ __forceinline__ float sgnroot(float v) {
    return (v == 0.f) ? 0.f : copysignf(sqrtf(fmaxf(fabsf(v), 1e-8f)), v);
}

__global__ void k_denom(const float* __restrict__ x) {
    int b = blockIdx.y;
    int slice = blockIdx.x;
    int tid = threadIdx.x;
    __shared__ float xs[CF], ts[CF];
#pragma unroll
    for (int j = 0; j < 8; j++) {
        xs[tid + j * 256] = x[(size_t)b * CF + tid + j * 256];
        ts[tid + j * 256] = d_t[(size_t)b * CF + tid + j * 256];
    }
    __syncthreads();
    int d = tid;
    for (int ai = 0; ai < 16; ai++) {
        int a = slice * 16 + ai;
        float acc = 0.f;
#pragma unroll
        for (int c = 0; c < C_; c++) {
            float v = xs[c * F_ + a] * ts[c * F_ + d] + xs[c * F_ + d] * ts[c * F_ + a];
            acc += sgnroot_abs(v);
        }
        d_denomh[((size_t)b * F_ + a) * F_ + d] = __float2half_rn(__fdividef(1.f, acc + 1e-7f));
    }
}

// ============================ K5: fp16 tensor-core zn/zx ============================
#define APITCH 40   // halves
__global__ void __launch_bounds__(256, 2) k_zn_mma(const float* __restrict__ x,
                                                   const float* __restrict__ nb) {
    int b = blockIdx.x >> 3, c = blockIdx.x & 7;
    int tid = threadIdx.x;
    int wid = tid >> 5, lid = tid & 31;
    int g = lid >> 2, tig = lid & 3;
    int A0 = wid * 32;

    __shared__ float xS[F_], tS[F_];
    __shared__ __half adjS[F_][APITCH];
    __shared__ __half nbS[64][APITCH];

    xS[tid] = x[(size_t)(b * C_ + c) * F_ + tid];
    tS[tid] = d_t[(size_t)(b * C_ + c) * F_ + tid];
    __syncthreads();

    float acc[4][4][4];
#pragma unroll
    for (int i = 0; i < 4; i++)
#pragma unroll
        for (int j = 0; j < 4; j++)
#pragma unroll
            for (int k = 0; k < 4; k++) acc[i][j][k] = 0.f;
    float zxAcc = 0.f;

    const int dl = tid & 31;
    const int w8 = tid >> 5;

    const uint32_t nbBase = smem_u32(nbS) + ((uint32_t)((lid & 15) * APITCH + (lid >> 4) * 8)) * 2;
    const uint32_t adjBase = smem_u32(adjS) +
        ((uint32_t)((A0 + ((lid >> 4) & 1) * 8 + (lid & 7)) * APITCH + ((lid >> 3) & 1) * 8)) * 2;

    for (int dt = 0; dt < 8; dt++) {
        const int d0 = dt * 32;
        const float xd = xS[d0 + dl], td = tS[d0 + dl];
        const __half* rden = d_denomh + (size_t)b * F_ * F_ + d0 + dl;
#pragma unroll
        for (int j = 0; j < 32; j++) {
            int a = w8 + j * 8;
            float v = xS[a] * td + xd * tS[a];
            float gg = sgnroot(v);
            adjS[a][dl] = __float2half_rn(gg * __half2float(rden[(size_t)a * F_]));
        }
#pragma unroll
        for (int j = 0; j < 8; j++) {
            int i = tid + j * 256;
            int n = i >> 5, d2 = i & 31;
            nbS[n][d2] = __float2half_rn(nb[((((size_t)b * N_) + n) * C_ + c) * F_ + d0 + d2]);
        }
        __syncthreads();

#pragma unroll
        for (int ks = 0; ks < 2; ks++) {
            const int kb = ks * 16;
            uint32_t a4[4][4], b2[4][2];
#pragma unroll
            for (int mt = 0; mt < 4; mt++)
                ldsm4(a4[mt][0], a4[mt][1], a4[mt][2], a4[mt][3],
                      nbBase + (uint32_t)(mt * 16 * APITCH + kb) * 2);
#pragma unroll
            for (int p = 0; p < 2; p++)
                ldsm4(b2[2 * p][0], b2[2 * p][1], b2[2 * p + 1][0], b2[2 * p + 1][1],
                      adjBase + (uint32_t)(p * 16 * APITCH + kb) * 2);
#pragma unroll
            for (int mt = 0; mt < 4; mt++)
#pragma unroll
                for (int nt = 0; nt < 4; nt++) {
                    asm volatile(
                        "mma.sync.aligned.m16n8k16.row.col.f32.f16.f16.f32 "
                        "{%0,%1,%2,%3}, {%4,%5,%6,%7}, {%8,%9}, {%0,%1,%2,%3};"
                        : "+f"(acc[mt][nt][0]), "+f"(acc[mt][nt][1]),
                          "+f"(acc[mt][nt][2]), "+f"(acc[mt][nt][3])
                        : "r"(a4[mt][0]), "r"(a4[mt][1]), "r"(a4[mt][2]), "r"(a4[mt][3]),
                          "r"(b2[nt][0]), "r"(b2[nt][1]));
                }
        }
        {
            int a = A0 + lid;
#pragma unroll
            for (int k2 = 0; k2 < 32; k2++) zxAcc += __half2float(adjS[a][k2]) * xS[d0 + k2];
        }
        __syncthreads();
    }

#pragma unroll
    for (int mt = 0; mt < 4; mt++) {
#pragma unroll
        for (int half = 0; half < 2; half++) {
            int n = mt * 16 + g + half * 8;
            __half* dst = d_Zh + ((((size_t)b * N_) + n) * C_ + c) * F_;
#pragma unroll
            for (int nt = 0; nt < 4; nt++) {
                int col = A0 + nt * 8 + 2 * tig;
                __half2 v = __floats2half2_rn(acc[mt][nt][half * 2], acc[mt][nt][half * 2 + 1]);
                *(__half2*)(dst + col) = v;
            }
        }
    }
    d_Zh[(size_t)(4096 + b) * CF + c * F_ + A0 + lid] = __float2half_rn(zxAcc);
}

// Convert Wc to fp16 (8 floats / thread)
__global__ void k_wc(const float* __restrict__ Wc) {
    size_t i = ((size_t)blockIdx.x * 256 + threadIdx.x) * 8;
    float4 v0 = *(const float4*)(Wc + i);
    float4 v1 = *(const float4*)(Wc + i + 4);
    __half2 h[4];
    h[0] = __floats2half2_rn(v0.x, v0.y);
    h[1] = __floats2half2_rn(v0.z, v0.w);
    h[2] = __floats2half2_rn(v1.x, v1.y);
    h[3] = __floats2half2_rn(v1.z, v1.w);
    *(uint4*)(d_Wch + i) = *(const uint4*)h;
}

// ============================ K6: fp16 mma GEMM, 3-stage pipeline ============================
#define PITCHH 72
#define BUFH (128 * PITCHH)                // halves per operand per stage
#define STAGE_B (2 * BUFH * 2)             // bytes per stage (A+B)
#define GEMM_SMEM (3 * STAGE_B)

__global__ void __launch_bounds__(256, 2) k_gemm_mma(float* __restrict__ out) {
    extern __shared__ __half smh[];
    const int tid = threadIdx.x;
    const int wid = tid >> 5, lid = tid & 31;
    const int wm = wid >> 2, wn = wid & 3;
    const int g = lid >> 2, tig = lid & 3;
    const int bm = blockIdx.y * 128, bo = blockIdx.x * 128;

    const int lrow = tid >> 3;
    const int jc = tid & 7;
    const uint32_t sBase = smem_u32(smh);
    const __half* Ag = d_Zh + (size_t)(bm + lrow) * CF + jc * 8;
    const __half* Bg = d_Wch + (size_t)(bo + lrow) * CF + jc * 8;
    const uint32_t swOff = (uint32_t)(lrow * PITCHH + jc * 8) * 2;

    // ldmatrix lane bases (stage 0)
    const uint32_t aBase = sBase + ((uint32_t)((wm * 64 + (lid & 15)) * PITCHH + (lid >> 4) * 8)) * 2;
    const uint32_t bBase = sBase + (uint32_t)BUFH * 2 +
        ((uint32_t)((wn * 32 + ((lid >> 4) & 1) * 8 + (lid & 7)) * PITCHH + ((lid >> 3) & 1) * 8)) * 2;

    float acc[4][4][4];
#pragma unroll
    for (int i = 0; i < 4; i++)
#pragma unroll
        for (int j = 0; j < 4; j++)
#pragma unroll
            for (int k = 0; k < 4; k++) acc[i][j][k] = 0.f;

    const int NKT = CF / 64;   // 32

    auto load_stage = [&](int stg, int kt) {
        uint32_t dA = sBase + (uint32_t)stg * STAGE_B + swOff;
        uint32_t dB = dA + (uint32_t)BUFH * 2;
        const __half* As = Ag + kt * 64;
        const __half* Bs = Bg + kt * 64;
#pragma unroll
        for (int p = 0; p < 4; p++) {
            cp16(dA + p * 32 * PITCHH * 2, As + (size_t)p * 32 * CF);
            cp16(dB + p * 32 * PITCHH * 2, Bs + (size_t)p * 32 * CF);
        }
        asm volatile("cp.async.commit_group;" ::: "memory");
    };

    load_stage(0, 0);
    load_stage(1, 1);

    int stg = 0;
    for (int kt = 0; kt < NKT; kt++) {
        if (kt == NKT - 1) asm volatile("cp.async.wait_group 0;" ::: "memory");
        else               asm volatile("cp.async.wait_group 1;" ::: "memory");
        __syncthreads();
        if (kt + 2 < NKT) {
            int ns = stg + 2; if (ns >= 3) ns -= 3;
            load_stage(ns, kt + 2);
        }
        const uint32_t aB = aBase + (uint32_t)stg * STAGE_B;
        const uint32_t bB = bBase + (uint32_t)stg * STAGE_B;
#pragma unroll
        for (int ks = 0; ks < 4; ks++) {
            const uint32_t kOff = (uint32_t)(ks * 16) * 2;
            uint32_t a[4][4], b[4][2];
#pragma unroll
            for (int mt = 0; mt < 4; mt++)
                ldsm4(a[mt][0], a[mt][1], a[mt][2], a[mt][3],
                      aB + (uint32_t)(mt * 16 * PITCHH) * 2 + kOff);
#pragma unroll
            for (int p = 0; p < 2; p++)
                ldsm4(b[2 * p][0], b[2 * p][1], b[2 * p + 1][0], b[2 * p + 1][1],
                      bB + (uint32_t)(p * 16 * PITCHH) * 2 + kOff);
#pragma unroll
            for (int mt = 0; mt < 4; mt++)
#pragma unroll
                for (int nt = 0; nt < 4; nt++) {
                    asm volatile(
                        "mma.sync.aligned.m16n8k16.row.col.f32.f16.f16.f32 "
                        "{%0,%1,%2,%3}, {%4,%5,%6,%7}, {%8,%9}, {%0,%1,%2,%3};"
                        : "+f"(acc[mt][nt][0]), "+f"(acc[mt][nt][1]),
                          "+f"(acc[mt][nt][2]), "+f"(acc[mt][nt][3])
                        : "r"(a[mt][0]), "r"(a[mt][1]), "r"(a[mt][2]), "r"(a[mt][3]),
                          "r"(b[nt][0]), "r"(b[nt][1]));
                }
        }
        if (++stg == 3) stg = 0;
    }

#pragma unroll
    for (int mt = 0; mt < 4; mt++) {
#pragma unroll
        for (int half = 0; half < 2; half++) {
            int m = bm + wm * 64 + mt * 16 + g + half * 8;
            float* dst;
            if (m < 4096)      dst = out + (size_t)B_ * OCOF + (size_t)m * OCOF;
            else if (m < 4160) dst = out + (size_t)(m - 4096) * OCOF;
            else               continue;
#pragma unroll
            for (int nt = 0; nt < 4; nt++) {
                int col = bo + wn * 32 + nt * 8 + 2 * tig;
                float2 v = make_float2(acc[mt][nt][half * 2], acc[mt][nt][half * 2 + 1]);
                *(float2*)(dst + col) = v;
            }
        }
    }
}

// ============================ launch ============================
extern "C" void kernel_launch(void* const* d_in, const int* in_sizes, int n_in,
                              void* d_out, int out_size) {
    (void)in_sizes; (void)n_in; (void)out_size;
    const float* x  = (const float*)d_in[0];
    const float* nb = (const float*)d_in[1];
    const float* W1 = (const float*)d_in[2];
    const float* W2 = (const float*)d_in[3];
    const float* Wc = (const float*)d_in[4];
    float* out = (float*)d_out;

    cudaFuncSetAttribute(k_gemm_mma, cudaFuncAttributeMaxDynamicSharedMemorySize, GEMM_SMEM);

    k_s12<<<B_ + B_ * N_, 256>>>(x, nb, W1, W2);
    k_t<<<B_ * C_, 256>>>(nb);
    k_denom<<<dim3(16, B_), 256>>>(x);
    k_wc<<<(OCOF * CF) / 2048, 256>>>(Wc);
    k_zn_mma<<<B_ * C_, 256>>>(x, nb);
    k_gemm_mma<<<dim3(OCOF / 128, MROWS / 128), 256, GEMM_SMEM>>>(out);
}